// round 1
// baseline (speedup 1.0000x reference)
#include <cuda_runtime.h>

// ---------------------------------------------------------------------------
// Net_25469156065564: PCNN forward pass, fp32 baseline.
//
// Pipeline:
//  1) build Xpad[b][l+2][750]  (word | pos1,pos2 | sdp*word), 2 zero rows pad
//  2) conv1 x3 as GEMM (K contiguous window over Xpad rows) + relu -> O1[b][l][300]
//  3) maxpool w=2 -> P[b][p][300]
//  4) conv2a (1x1) as GEMM -> A2pad[b][p+1][200] (rows 0,51 stay zero)
//  5) conv2b (kw=3) as GEMM + relu -> O3[b][p][300]
//  6) max over p -> H[b][300]
//  7) FC 300->100->50->15 -> out
// ---------------------------------------------------------------------------

#define BATCH 512
#define LEN   100
#define XROWS 104
#define XC    750

#define K1P  752    // 750 padded to 16
#define K3P  2256   // 2250
#define K5P  3760   // 3750
#define K2AP 304    // 300
#define K2BP 608    // 600

// scratch (zero-initialized; pad rows / slack never written)
__device__ float g_Xpad[BATCH * XROWS * XC + 64];
__device__ float g_O1[BATCH * LEN * 300];
__device__ float g_P [BATCH * 50 * 300 + 64];
__device__ float g_A2[BATCH * 52 * 200 + 64];
__device__ float g_O3[BATCH * 50 * 300];
__device__ float g_H [BATCH * 300];
__device__ float g_W1 [100 * K1P];
__device__ float g_W3 [100 * K3P];
__device__ float g_W5 [100 * K5P];
__device__ float g_W2a[200 * K2AP];
__device__ float g_W2b[300 * K2BP];

// ---------------------------------------------------------------------------
// Weight re-layouts (K padded to mult of 16, zeros in tail).
// conv1 K index: kw*750 + h*250 + ci  (kw absent for w11)
// ---------------------------------------------------------------------------
__global__ void prep_weights(const float* __restrict__ w11,
                             const float* __restrict__ w13,
                             const float* __restrict__ w15,
                             const float* __restrict__ w2a,
                             const float* __restrict__ w2b)
{
    int which = blockIdx.y;
    int idx = blockIdx.x * 256 + threadIdx.x;
    if (which == 0) {                       // w11 (100,250,3,1) -> [100][752]
        if (idx >= 100 * K1P) return;
        int o = idx / K1P, k = idx % K1P;
        float v = 0.f;
        if (k < 750) { int h = k / 250, ci = k % 250; v = w11[o * 750 + ci * 3 + h]; }
        g_W1[idx] = v;
    } else if (which == 1) {                // w13 (100,250,3,3) -> [100][2256]
        if (idx >= 100 * K3P) return;
        int o = idx / K3P, k = idx % K3P;
        float v = 0.f;
        if (k < 2250) {
            int kw = k / 750, r = k % 750, h = r / 250, ci = r % 250;
            v = w13[o * 2250 + ci * 9 + h * 3 + kw];
        }
        g_W3[idx] = v;
    } else if (which == 2) {                // w15 (100,250,3,5) -> [100][3760]
        if (idx >= 100 * K5P) return;
        int o = idx / K5P, k = idx % K5P;
        float v = 0.f;
        if (k < 3750) {
            int kw = k / 750, r = k % 750, h = r / 250, ci = r % 250;
            v = w15[o * 3750 + ci * 15 + h * 5 + kw];
        }
        g_W5[idx] = v;
    } else if (which == 3) {                // w2b (300,200,1,3) -> [300][608], k=kw*200+c2
        if (idx >= 300 * K2BP) return;
        int o = idx / K2BP, k = idx % K2BP;
        float v = 0.f;
        if (k < 600) { int kw = k / 200, c2 = k % 200; v = w2b[o * 600 + c2 * 3 + kw]; }
        g_W2b[idx] = v;
    } else {                                // w2a (200,300,1,1) -> [200][304]
        if (idx >= 200 * K2AP) return;
        int o = idx / K2AP, k = idx % K2AP;
        g_W2a[idx] = (k < 300) ? w2a[o * 300 + k] : 0.f;
    }
}

// ---------------------------------------------------------------------------
// Build Xpad rows 2..101 (rows 0,1,102,103 remain zero from static init).
// c: [0,250) word, [250,375) pos1, [375,500) pos2, [500,750) sdp*word
// ---------------------------------------------------------------------------
__global__ void build_x(const int* __restrict__ tok,
                        const int* __restrict__ p1m,
                        const int* __restrict__ p2m,
                        const float* __restrict__ sdp,
                        const float* __restrict__ wemb,
                        const float* __restrict__ p1e,
                        const float* __restrict__ p2e)
{
    int blk = blockIdx.x;
    int b = blk / LEN, l = blk % LEN;
    int t  = tok[b * LEN + l];
    int p1 = p1m[b * LEN + l];
    int p2 = p2m[b * LEN + l];
    float s = sdp[b * LEN + l];
    float* row = g_Xpad + ((long)(b * XROWS + l + 2)) * XC;
    int tid = threadIdx.x;
    if (tid < 250) {
        float w = wemb[(long)t * 250 + tid];
        row[tid] = w;
        row[500 + tid] = s * w;
    }
    if (tid < 125) {
        row[250 + tid] = p1e[p1 * 125 + tid];
        row[375 + tid] = p2e[p2 * 125 + tid];
    }
}

// ---------------------------------------------------------------------------
// Generic GEMM over virtual-column X:
//   C[m, n] = bias[m] + sum_k W[m*Kp + k] * X[b*sB + l*sL + k]   (n = b*Lout + l)
//   out[b*oB + l*oL + mOff + m], optional relu.
// Tiles: BM=128, BN=64, BK=16, 256 threads, 8x4 per thread.
// X columns are only 8B-aligned for conv1 (stride 750 floats) -> float2 gmem loads.
// K tails handled via zero-padded weights + slack in X buffers.
// ---------------------------------------------------------------------------
__global__ __launch_bounds__(256)
void gemm_conv(const float* __restrict__ W, const float* __restrict__ bias,
               const float* __restrict__ X, float* __restrict__ out,
               int M, int Kp, int Lout,
               long sB, int sL, long oB, int oL, int mOff, int doRelu)
{
    __shared__ float As[16][128];
    __shared__ float Bs[16][64];

    int tid = threadIdx.x;
    int tx = tid & 15;          // n group (4 cols)
    int ty = tid >> 4;          // m group (8 rows)
    int mBase = blockIdx.y * 128;
    int nBase = blockIdx.x * 64;

    // --- B-tile load mapping: 64 cols x 16 k, 4 threads per col (4 k each) ---
    int bcol = tid >> 2;
    int bk4  = (tid & 3) * 4;
    {
        int n = nBase + bcol;
        int bb = n / Lout, ll = n % Lout;
        X += (long)bb * sB + (long)ll * sL + bk4;   // per-thread column ptr
    }

    // --- A-tile load mapping: 128 rows x 16 k, 2 threads per row (8 k each) ---
    int am  = tid >> 1;
    int ak8 = (tid & 1) * 8;
    const float* aPtr = W + (long)(mBase + am) * Kp + ak8;
    bool aValid = (mBase + am) < M;

    float acc[8][4];
#pragma unroll
    for (int i = 0; i < 8; i++)
#pragma unroll
        for (int j = 0; j < 4; j++) acc[i][j] = 0.f;

    int nTiles = Kp >> 4;
    for (int kt = 0; kt < nTiles; kt++) {
        float4 a0 = make_float4(0,0,0,0), a1 = make_float4(0,0,0,0);
        if (aValid) {
            a0 = *(const float4*)(aPtr);
            a1 = *(const float4*)(aPtr + 4);
        }
        As[ak8+0][am] = a0.x; As[ak8+1][am] = a0.y;
        As[ak8+2][am] = a0.z; As[ak8+3][am] = a0.w;
        As[ak8+4][am] = a1.x; As[ak8+5][am] = a1.y;
        As[ak8+6][am] = a1.z; As[ak8+7][am] = a1.w;

        float2 b0 = *(const float2*)(X);
        float2 b1 = *(const float2*)(X + 2);
        Bs[bk4+0][bcol] = b0.x; Bs[bk4+1][bcol] = b0.y;
        Bs[bk4+2][bcol] = b1.x; Bs[bk4+3][bcol] = b1.y;

        __syncthreads();

#pragma unroll
        for (int kk = 0; kk < 16; kk++) {
            float ar[8], br[4];
#pragma unroll
            for (int i = 0; i < 8; i++) ar[i] = As[kk][ty * 8 + i];
#pragma unroll
            for (int j = 0; j < 4; j++) br[j] = Bs[kk][tx * 4 + j];
#pragma unroll
            for (int i = 0; i < 8; i++)
#pragma unroll
                for (int j = 0; j < 4; j++) acc[i][j] += ar[i] * br[j];
        }
        __syncthreads();
        aPtr += 16;
        X += 16;
    }

#pragma unroll
    for (int i = 0; i < 8; i++) {
        int m = mBase + ty * 8 + i;
        if (m >= M) continue;
        float bv = bias[m];
#pragma unroll
        for (int j = 0; j < 4; j++) {
            int nn = nBase + tx * 4 + j;
            int b2 = nn / Lout, l2 = nn % Lout;
            float v = acc[i][j] + bv;
            if (doRelu) v = fmaxf(v, 0.f);
            out[(long)b2 * oB + (long)l2 * oL + mOff + m] = v;
        }
    }
}

// maxpool width 2 over l: O1[b][2p..2p+1][c] -> P[b][p][c]
__global__ void pool1()
{
    int blk = blockIdx.x;
    int b = blk / 50, p = blk % 50;
    const float* r0 = g_O1 + ((long)b * LEN + 2 * p) * 300;
    float* dst = g_P + ((long)b * 50 + p) * 300;
    for (int c = threadIdx.x; c < 300; c += blockDim.x)
        dst[c] = fmaxf(r0[c], r0[300 + c]);
}

// max over all 50 positions: O3[b][p][c] -> H[b][c]
__global__ void pool3()
{
    int b = blockIdx.x;
    for (int c = threadIdx.x; c < 300; c += blockDim.x) {
        const float* src = g_O3 + (long)b * 15000 + c;
        float mx = src[0];
        for (int p = 1; p < 50; p++) mx = fmaxf(mx, src[p * 300]);
        g_H[b * 300 + c] = mx;
    }
}

// FC chain: 300 -> 100 (relu) -> 50 (relu) -> 15
__global__ void fc_chain(const float* __restrict__ d1w, const float* __restrict__ d1b,
                         const float* __restrict__ d2w, const float* __restrict__ d2b,
                         const float* __restrict__ d3w, const float* __restrict__ d3b,
                         float* __restrict__ out)
{
    __shared__ float h0[300], h1[100], h2[50];
    int b = blockIdx.x, tid = threadIdx.x;
    for (int i = tid; i < 300; i += 128) h0[i] = g_H[b * 300 + i];
    __syncthreads();
    if (tid < 100) {
        float s = d1b[tid];
        for (int k = 0; k < 300; k++) s += h0[k] * d1w[k * 100 + tid];
        h1[tid] = fmaxf(s, 0.f);
    }
    __syncthreads();
    if (tid < 50) {
        float s = d2b[tid];
        for (int k = 0; k < 100; k++) s += h1[k] * d2w[k * 50 + tid];
        h2[tid] = fmaxf(s, 0.f);
    }
    __syncthreads();
    if (tid < 15) {
        float s = d3b[tid];
        for (int k = 0; k < 50; k++) s += h2[k] * d3w[k * 15 + tid];
        out[b * 15 + tid] = s;
    }
}

extern "C" void kernel_launch(void* const* d_in, const int* in_sizes, int n_in,
                              void* d_out, int out_size)
{
    const int*   tok  = (const int*)  d_in[0];
    const int*   p1m  = (const int*)  d_in[1];
    const int*   p2m  = (const int*)  d_in[2];
    const float* sdp  = (const float*)d_in[3];
    const float* wemb = (const float*)d_in[4];
    const float* p1e  = (const float*)d_in[5];
    const float* p2e  = (const float*)d_in[6];
    const float* w11  = (const float*)d_in[7];
    const float* b11  = (const float*)d_in[8];
    const float* w13  = (const float*)d_in[9];
    const float* b13  = (const float*)d_in[10];
    const float* w15  = (const float*)d_in[11];
    const float* b15  = (const float*)d_in[12];
    const float* w2a  = (const float*)d_in[13];
    const float* b2a  = (const float*)d_in[14];
    const float* w2b  = (const float*)d_in[15];
    const float* b2b  = (const float*)d_in[16];
    const float* d1w  = (const float*)d_in[17];
    const float* d1b  = (const float*)d_in[18];
    const float* d2w  = (const float*)d_in[19];
    const float* d2b  = (const float*)d_in[20];
    const float* d3w  = (const float*)d_in[21];
    const float* d3b  = (const float*)d_in[22];

    float *Xpad, *O1, *P, *A2, *O3, *W1, *W3, *W5, *W2a, *W2b;
    cudaGetSymbolAddress((void**)&Xpad, g_Xpad);
    cudaGetSymbolAddress((void**)&O1,  g_O1);
    cudaGetSymbolAddress((void**)&P,   g_P);
    cudaGetSymbolAddress((void**)&A2,  g_A2);
    cudaGetSymbolAddress((void**)&O3,  g_O3);
    cudaGetSymbolAddress((void**)&W1,  g_W1);
    cudaGetSymbolAddress((void**)&W3,  g_W3);
    cudaGetSymbolAddress((void**)&W5,  g_W5);
    cudaGetSymbolAddress((void**)&W2a, g_W2a);
    cudaGetSymbolAddress((void**)&W2b, g_W2b);

    // weight re-layout (largest section: 100*3760 = 376000 elems)
    prep_weights<<<dim3((376000 + 255) / 256, 5), 256>>>(w11, w13, w15, w2a, w2b);

    // input assembly
    build_x<<<BATCH * LEN, 256>>>(tok, p1m, p2m, sdp, wemb, p1e, p2e);

    // conv1 (3 GEMMs over sliding contiguous windows of Xpad), relu fused
    // n = b*100 + l ; col = Xpad + b*78000 + (l + 2 - pad)*750
    gemm_conv<<<dim3(51200 / 64, 1), 256>>>(W1, b11, Xpad + 2 * 750, O1,
                                            100, K1P, 100, (long)XROWS * XC, XC,
                                            30000, 300, 0, 1);
    gemm_conv<<<dim3(51200 / 64, 1), 256>>>(W3, b13, Xpad + 750, O1,
                                            100, K3P, 100, (long)XROWS * XC, XC,
                                            30000, 300, 100, 1);
    gemm_conv<<<dim3(51200 / 64, 1), 256>>>(W5, b15, Xpad, O1,
                                            100, K5P, 100, (long)XROWS * XC, XC,
                                            30000, 300, 200, 1);

    pool1<<<BATCH * 50, 256>>>();

    // conv2a (1x1): writes into padded A2 rows 1..50 (rows 0,51 stay zero)
    gemm_conv<<<dim3(25600 / 64, 2), 256>>>(W2a, b2a, P, A2 + 200,
                                            200, K2AP, 50, 15000, 300,
                                            10400, 200, 0, 0);

    // conv2b (kw=3, pad=1): contiguous 3-row window of A2pad, relu fused
    gemm_conv<<<dim3(25600 / 64, 3), 256>>>(W2b, b2b, A2, O3,
                                            300, K2BP, 50, 10400, 200,
                                            15000, 300, 0, 1);

    pool3<<<BATCH, 256>>>();

    fc_chain<<<BATCH, 128>>>(d1w, d1b, d2w, d2b, d3w, d3b, (float*)d_out);
}

// round 2
// speedup vs baseline: 2.4293x; 2.4293x over previous
#include <cuda_runtime.h>

// ---------------------------------------------------------------------------
// Net_25469156065564: PCNN forward, tf32 tensor-core GEMMs (mma.sync m16n8k8).
//
//  1) build Xpad[b][l+2][750]  (word | pos1,pos2 | sdp*word), 2 zero pad rows
//  2) conv1 x3 as GEMM (contiguous K window over Xpad rows) + relu -> O1
//  3) maxpool w=2 -> P
//  4) conv2a (1x1) GEMM -> A2pad (rows 0,51 zero)
//  5) conv2b (kw=3) GEMM + relu -> O3
//  6) max over positions -> H
//  7) FC 300->100->50->15
// ---------------------------------------------------------------------------

#define BATCH 512
#define LEN   100
#define XROWS 104
#define XC    750

// K padded to multiples of 32 (zero weights in tail)
#define K1P  768
#define K3P  2272
#define K5P  3776
#define K2AP 320
#define K2BP 608

__device__ float g_Xpad[BATCH * XROWS * XC + 64];
__device__ float g_O1[BATCH * LEN * 300];
__device__ float g_P [BATCH * 50 * 300 + 64];
__device__ float g_A2[BATCH * 52 * 200 + 64];
__device__ float g_O3[BATCH * 50 * 300];
__device__ float g_H [BATCH * 300];
__device__ float g_W1 [100 * K1P];
__device__ float g_W3 [100 * K3P];
__device__ float g_W5 [100 * K5P];
__device__ float g_W2a[200 * K2AP];
__device__ float g_W2b[300 * K2BP];

// ---------------------------------------------------------------------------
__global__ void prep_weights(const float* __restrict__ w11,
                             const float* __restrict__ w13,
                             const float* __restrict__ w15,
                             const float* __restrict__ w2a,
                             const float* __restrict__ w2b)
{
    int which = blockIdx.y;
    int idx = blockIdx.x * 256 + threadIdx.x;
    if (which == 0) {                       // w11 (100,250,3,1) -> [100][768]
        if (idx >= 100 * K1P) return;
        int o = idx / K1P, k = idx % K1P;
        float v = 0.f;
        if (k < 750) { int h = k / 250, ci = k % 250; v = w11[o * 750 + ci * 3 + h]; }
        g_W1[idx] = v;
    } else if (which == 1) {                // w13 (100,250,3,3) -> [100][2272]
        if (idx >= 100 * K3P) return;
        int o = idx / K3P, k = idx % K3P;
        float v = 0.f;
        if (k < 2250) {
            int kw = k / 750, r = k % 750, h = r / 250, ci = r % 250;
            v = w13[o * 2250 + ci * 9 + h * 3 + kw];
        }
        g_W3[idx] = v;
    } else if (which == 2) {                // w15 (100,250,3,5) -> [100][3776]
        if (idx >= 100 * K5P) return;
        int o = idx / K5P, k = idx % K5P;
        float v = 0.f;
        if (k < 3750) {
            int kw = k / 750, r = k % 750, h = r / 250, ci = r % 250;
            v = w15[o * 3750 + ci * 15 + h * 5 + kw];
        }
        g_W5[idx] = v;
    } else if (which == 3) {                // w2b (300,200,1,3) -> [300][608]
        if (idx >= 300 * K2BP) return;
        int o = idx / K2BP, k = idx % K2BP;
        float v = 0.f;
        if (k < 600) { int kw = k / 200, c2 = k % 200; v = w2b[o * 600 + c2 * 3 + kw]; }
        g_W2b[idx] = v;
    } else {                                // w2a (200,300,1,1) -> [200][320]
        if (idx >= 200 * K2AP) return;
        int o = idx / K2AP, k = idx % K2AP;
        g_W2a[idx] = (k < 300) ? w2a[o * 300 + k] : 0.f;
    }
}

// ---------------------------------------------------------------------------
__global__ void build_x(const int* __restrict__ tok,
                        const int* __restrict__ p1m,
                        const int* __restrict__ p2m,
                        const float* __restrict__ sdp,
                        const float* __restrict__ wemb,
                        const float* __restrict__ p1e,
                        const float* __restrict__ p2e)
{
    int blk = blockIdx.x;
    int b = blk / LEN, l = blk % LEN;
    int t  = tok[b * LEN + l];
    int p1 = p1m[b * LEN + l];
    int p2 = p2m[b * LEN + l];
    float s = sdp[b * LEN + l];
    float* row = g_Xpad + ((long)(b * XROWS + l + 2)) * XC;
    int tid = threadIdx.x;
    if (tid < 250) {
        float w = wemb[(long)t * 250 + tid];
        row[tid] = w;
        row[500 + tid] = s * w;
    }
    if (tid < 125) {
        row[250 + tid] = p1e[p1 * 125 + tid];
        row[375 + tid] = p2e[p2 * 125 + tid];
    }
}

// ---------------------------------------------------------------------------
// tf32 tensor-core GEMM over virtual-column X:
//   C[m, n] = bias[m] + sum_k W[m*Kp+k] * X[(n/LOUT)*sB + (n%LOUT)*sL + k]
// CTA tile 128M x 128N, BK=32, 256 threads = 8 warps (4M x 2N), warp 32x64.
// mma.sync.m16n8k8.tf32, fp32 accumulate. Conflict-free frag LDS via padded
// strides: As stride 36 (bank = 4r+c), Bs stride 136 (bank = 8c+e).
// ---------------------------------------------------------------------------
__device__ __forceinline__ unsigned f2tf(float f) {
    unsigned u;
    asm("cvt.rna.tf32.f32 %0, %1;" : "=r"(u) : "f"(f));
    return u;
}

#define SA 36
#define SB 136

template<int LOUT>
__global__ __launch_bounds__(256)
void gemm_mma(const float* __restrict__ W, const float* __restrict__ bias,
              const float* __restrict__ X, float* __restrict__ out,
              int M, int Kp, long sB, int sL, long oB, int oL,
              int mOff, int doRelu)
{
    __shared__ float As[128 * SA];   // [m][k], k in [0,32)
    __shared__ float Bs[32 * SB];    // [k][n], n in [0,128)

    int tid = threadIdx.x;
    int lane = tid & 31;
    int warp = tid >> 5;
    int wm = warp & 3;               // warp M index (4)
    int wn = warp >> 2;              // warp N index (2)
    int lr = lane >> 2;              // 0..7
    int lc = lane & 3;               // 0..3

    int mBase = blockIdx.y * 128;
    int nBase = blockIdx.x * 128;

    // global A mapping: thread -> (row tile 0..127, khalf 0/16)
    int aRow  = tid >> 1;
    int aKoff = (tid & 1) * 16;
    const float* aPtr = W + (long)(mBase + aRow) * Kp + aKoff;
    bool aValid = (mBase + aRow) < M;

    // global B mapping: thread -> (col tile 0..127, khalf 0/16)
    int bCol  = tid >> 1;
    int bKoff = (tid & 1) * 16;
    const float* bPtr;
    {
        int n = nBase + bCol;
        int bb = n / LOUT, ll = n % LOUT;
        bPtr = X + (long)bb * sB + (long)ll * sL + bKoff;
    }

    float acc[2][8][4];
#pragma unroll
    for (int i = 0; i < 2; i++)
#pragma unroll
        for (int j = 0; j < 8; j++)
#pragma unroll
            for (int q = 0; q < 4; q++) acc[i][j][q] = 0.f;

    // prefetch chunk 0
    float4 aR[4];
    float2 bR[8];
#pragma unroll
    for (int i = 0; i < 4; i++)
        aR[i] = aValid ? *(const float4*)(aPtr + 4 * i)
                       : make_float4(0.f, 0.f, 0.f, 0.f);
#pragma unroll
    for (int i = 0; i < 8; i++) bR[i] = *(const float2*)(bPtr + 2 * i);

    int nChunks = Kp >> 5;
    for (int c = 0; c < nChunks; c++) {
        // stage regs -> smem (tf32-converted bit patterns)
        unsigned* asU = (unsigned*)(As + aRow * SA + aKoff);
#pragma unroll
        for (int i = 0; i < 4; i++) {
            asU[4 * i + 0] = f2tf(aR[i].x);
            asU[4 * i + 1] = f2tf(aR[i].y);
            asU[4 * i + 2] = f2tf(aR[i].z);
            asU[4 * i + 3] = f2tf(aR[i].w);
        }
#pragma unroll
        for (int i = 0; i < 8; i++) {
            ((unsigned*)Bs)[(bKoff + 2 * i + 0) * SB + bCol] = f2tf(bR[i].x);
            ((unsigned*)Bs)[(bKoff + 2 * i + 1) * SB + bCol] = f2tf(bR[i].y);
        }
        __syncthreads();

        // prefetch next chunk (latency hidden under mma)
        if (c + 1 < nChunks) {
            aPtr += 32; bPtr += 32;
#pragma unroll
            for (int i = 0; i < 4; i++)
                aR[i] = aValid ? *(const float4*)(aPtr + 4 * i)
                               : make_float4(0.f, 0.f, 0.f, 0.f);
#pragma unroll
            for (int i = 0; i < 8; i++) bR[i] = *(const float2*)(bPtr + 2 * i);
        }

        const unsigned* AsU = (const unsigned*)As;
        const unsigned* BsU = (const unsigned*)Bs;
#pragma unroll
        for (int kk = 0; kk < 4; kk++) {
            int k0 = kk * 8;
            unsigned af[2][4];
#pragma unroll
            for (int mi = 0; mi < 2; mi++) {
                int rb = wm * 32 + mi * 16;
                af[mi][0] = AsU[(rb + lr) * SA + k0 + lc];
                af[mi][1] = AsU[(rb + 8 + lr) * SA + k0 + lc];
                af[mi][2] = AsU[(rb + lr) * SA + k0 + 4 + lc];
                af[mi][3] = AsU[(rb + 8 + lr) * SA + k0 + 4 + lc];
            }
#pragma unroll
            for (int ni = 0; ni < 8; ni++) {
                int nb = wn * 64 + ni * 8;
                unsigned b0 = BsU[(k0 + lc) * SB + nb + lr];
                unsigned b1 = BsU[(k0 + 4 + lc) * SB + nb + lr];
#pragma unroll
                for (int mi = 0; mi < 2; mi++) {
                    asm volatile(
                        "mma.sync.aligned.m16n8k8.row.col.f32.tf32.tf32.f32 "
                        "{%0,%1,%2,%3}, {%4,%5,%6,%7}, {%8,%9}, {%0,%1,%2,%3};"
                        : "+f"(acc[mi][ni][0]), "+f"(acc[mi][ni][1]),
                          "+f"(acc[mi][ni][2]), "+f"(acc[mi][ni][3])
                        : "r"(af[mi][0]), "r"(af[mi][1]),
                          "r"(af[mi][2]), "r"(af[mi][3]),
                          "r"(b0), "r"(b1));
                }
            }
        }
        __syncthreads();
    }

    // epilogue
#pragma unroll
    for (int mi = 0; mi < 2; mi++) {
        int r0 = mBase + wm * 32 + mi * 16 + lr;
        int r1 = r0 + 8;
        float bv0 = (r0 < M) ? bias[r0] : 0.f;
        float bv1 = (r1 < M) ? bias[r1] : 0.f;
#pragma unroll
        for (int ni = 0; ni < 8; ni++) {
            int cb = nBase + wn * 64 + ni * 8 + lc * 2;
#pragma unroll
            for (int cc = 0; cc < 2; cc++) {
                int n = cb + cc;
                int b2 = n / LOUT, l2 = n % LOUT;
                long base = (long)b2 * oB + (long)l2 * oL + mOff;
                if (r0 < M) {
                    float v = acc[mi][ni][cc] + bv0;
                    if (doRelu) v = fmaxf(v, 0.f);
                    out[base + r0] = v;
                }
                if (r1 < M) {
                    float v = acc[mi][ni][2 + cc] + bv1;
                    if (doRelu) v = fmaxf(v, 0.f);
                    out[base + r1] = v;
                }
            }
        }
    }
}

// maxpool width 2 over l
__global__ void pool1()
{
    int blk = blockIdx.x;
    int b = blk / 50, p = blk % 50;
    const float* r0 = g_O1 + ((long)b * LEN + 2 * p) * 300;
    float* dst = g_P + ((long)b * 50 + p) * 300;
    for (int c = threadIdx.x; c < 300; c += blockDim.x)
        dst[c] = fmaxf(r0[c], r0[300 + c]);
}

// max over all 50 positions
__global__ void pool3()
{
    int b = blockIdx.x;
    for (int c = threadIdx.x; c < 300; c += blockDim.x) {
        const float* src = g_O3 + (long)b * 15000 + c;
        float mx = src[0];
        for (int p = 1; p < 50; p++) mx = fmaxf(mx, src[p * 300]);
        g_H[b * 300 + c] = mx;
    }
}

// FC chain: 300 -> 100 (relu) -> 50 (relu) -> 15
__global__ void fc_chain(const float* __restrict__ d1w, const float* __restrict__ d1b,
                         const float* __restrict__ d2w, const float* __restrict__ d2b,
                         const float* __restrict__ d3w, const float* __restrict__ d3b,
                         float* __restrict__ out)
{
    __shared__ float h0[300], h1[100], h2[50];
    int b = blockIdx.x, tid = threadIdx.x;
    for (int i = tid; i < 300; i += 128) h0[i] = g_H[b * 300 + i];
    __syncthreads();
    if (tid < 100) {
        float s = d1b[tid];
        for (int k = 0; k < 300; k++) s += h0[k] * d1w[k * 100 + tid];
        h1[tid] = fmaxf(s, 0.f);
    }
    __syncthreads();
    if (tid < 50) {
        float s = d2b[tid];
        for (int k = 0; k < 100; k++) s += h1[k] * d2w[k * 50 + tid];
        h2[tid] = fmaxf(s, 0.f);
    }
    __syncthreads();
    if (tid < 15) {
        float s = d3b[tid];
        for (int k = 0; k < 50; k++) s += h2[k] * d3w[k * 15 + tid];
        out[b * 15 + tid] = s;
    }
}

extern "C" void kernel_launch(void* const* d_in, const int* in_sizes, int n_in,
                              void* d_out, int out_size)
{
    const int*   tok  = (const int*)  d_in[0];
    const int*   p1m  = (const int*)  d_in[1];
    const int*   p2m  = (const int*)  d_in[2];
    const float* sdp  = (const float*)d_in[3];
    const float* wemb = (const float*)d_in[4];
    const float* p1e  = (const float*)d_in[5];
    const float* p2e  = (const float*)d_in[6];
    const float* w11  = (const float*)d_in[7];
    const float* b11  = (const float*)d_in[8];
    const float* w13  = (const float*)d_in[9];
    const float* b13  = (const float*)d_in[10];
    const float* w15  = (const float*)d_in[11];
    const float* b15  = (const float*)d_in[12];
    const float* w2a  = (const float*)d_in[13];
    const float* b2a  = (const float*)d_in[14];
    const float* w2b  = (const float*)d_in[15];
    const float* b2b  = (const float*)d_in[16];
    const float* d1w  = (const float*)d_in[17];
    const float* d1b  = (const float*)d_in[18];
    const float* d2w  = (const float*)d_in[19];
    const float* d2b  = (const float*)d_in[20];
    const float* d3w  = (const float*)d_in[21];
    const float* d3b  = (const float*)d_in[22];

    float *Xpad, *O1, *P, *A2, *O3, *W1, *W3, *W5, *W2a, *W2b;
    cudaGetSymbolAddress((void**)&Xpad, g_Xpad);
    cudaGetSymbolAddress((void**)&O1,  g_O1);
    cudaGetSymbolAddress((void**)&P,   g_P);
    cudaGetSymbolAddress((void**)&A2,  g_A2);
    cudaGetSymbolAddress((void**)&O3,  g_O3);
    cudaGetSymbolAddress((void**)&W1,  g_W1);
    cudaGetSymbolAddress((void**)&W3,  g_W3);
    cudaGetSymbolAddress((void**)&W5,  g_W5);
    cudaGetSymbolAddress((void**)&W2a, g_W2a);
    cudaGetSymbolAddress((void**)&W2b, g_W2b);

    // weight re-layout (largest section: 100*3776 = 377600 elems)
    prep_weights<<<dim3((377600 + 255) / 256, 5), 256>>>(w11, w13, w15, w2a, w2b);

    // input assembly
    build_x<<<BATCH * LEN, 256>>>(tok, p1m, p2m, sdp, wemb, p1e, p2e);

    // conv1: N = 512*100 = 51200 -> 400 N-tiles, M=100 -> 1 M-tile
    gemm_mma<100><<<dim3(400, 1), 256>>>(W1, b11, Xpad + 2 * 750, O1,
                                         100, K1P, (long)XROWS * XC, XC,
                                         30000, 300, 0, 1);
    gemm_mma<100><<<dim3(400, 1), 256>>>(W3, b13, Xpad + 750, O1,
                                         100, K3P, (long)XROWS * XC, XC,
                                         30000, 300, 100, 1);
    gemm_mma<100><<<dim3(400, 1), 256>>>(W5, b15, Xpad, O1,
                                         100, K5P, (long)XROWS * XC, XC,
                                         30000, 300, 200, 1);

    pool1<<<BATCH * 50, 256>>>();

    // conv2a (1x1): N = 512*50 = 25600 -> 200 N-tiles, M=200 -> 2 M-tiles
    gemm_mma<50><<<dim3(200, 2), 256>>>(W2a, b2a, P, A2 + 200,
                                        200, K2AP, 15000, 300,
                                        10400, 200, 0, 0);

    // conv2b (kw=3, pad=1): M=300 -> 3 M-tiles
    gemm_mma<50><<<dim3(200, 3), 256>>>(W2b, b2b, A2, O3,
                                        300, K2BP, 10400, 200,
                                        15000, 300, 0, 1);

    pool3<<<BATCH, 256>>>();

    fc_chain<<<BATCH, 128>>>(d1w, d1b, d2w, d2b, d3w, d3b, (float*)d_out);
}

// round 3
// speedup vs baseline: 3.6619x; 1.5074x over previous
#include <cuda_runtime.h>

// ---------------------------------------------------------------------------
// Net_25469156065564: PCNN forward. tf32 mma.sync GEMMs fed by cp.async
// double-buffered pipelines; all GEMM inputs pre-converted to tf32 bits.
// ---------------------------------------------------------------------------

#define BATCH 512
#define LEN   100
#define XROWS 104
#define XC    750

// K padded to multiples of 32 (zero weights in tail)
#define K1P  768
#define K3P  2272
#define K5P  3776
#define K2AP 320
#define K2BP 608

__device__ __align__(16) float g_Xpad[BATCH * XROWS * XC + 64];
__device__ __align__(16) float g_O1[BATCH * LEN * 300];
__device__ __align__(16) float g_P [BATCH * 50 * 300 + 64];
__device__ __align__(16) float g_A2[BATCH * 52 * 200 + 64];
__device__ __align__(16) float g_O3[BATCH * 50 * 300];
__device__ __align__(16) float g_H [BATCH * 300];
// weight arrays padded to 128-row multiples (pad rows stay zero)
__device__ __align__(16) float g_W1 [128 * K1P];
__device__ __align__(16) float g_W3 [128 * K3P];
__device__ __align__(16) float g_W5 [128 * K5P];
__device__ __align__(16) float g_W2a[256 * K2AP];
__device__ __align__(16) float g_W2b[384 * K2BP];

__device__ __forceinline__ float f2tf_f(float f) {
    unsigned u;
    asm("cvt.rna.tf32.f32 %0, %1;" : "=r"(u) : "f"(f));
    return __uint_as_float(u);
}

// ---------------------------------------------------------------------------
__global__ void prep_weights(const float* __restrict__ w11,
                             const float* __restrict__ w13,
                             const float* __restrict__ w15,
                             const float* __restrict__ w2a,
                             const float* __restrict__ w2b)
{
    int which = blockIdx.y;
    int idx = blockIdx.x * 256 + threadIdx.x;
    if (which == 0) {                       // w11 (100,250,3,1) -> [100][768]
        if (idx >= 100 * K1P) return;
        int o = idx / K1P, k = idx % K1P;
        float v = 0.f;
        if (k < 750) { int h = k / 250, ci = k % 250; v = w11[o * 750 + ci * 3 + h]; }
        g_W1[idx] = f2tf_f(v);
    } else if (which == 1) {                // w13 (100,250,3,3) -> [100][2272]
        if (idx >= 100 * K3P) return;
        int o = idx / K3P, k = idx % K3P;
        float v = 0.f;
        if (k < 2250) {
            int kw = k / 750, r = k % 750, h = r / 250, ci = r % 250;
            v = w13[o * 2250 + ci * 9 + h * 3 + kw];
        }
        g_W3[idx] = f2tf_f(v);
    } else if (which == 2) {                // w15 (100,250,3,5) -> [100][3776]
        if (idx >= 100 * K5P) return;
        int o = idx / K5P, k = idx % K5P;
        float v = 0.f;
        if (k < 3750) {
            int kw = k / 750, r = k % 750, h = r / 250, ci = r % 250;
            v = w15[o * 3750 + ci * 15 + h * 5 + kw];
        }
        g_W5[idx] = f2tf_f(v);
    } else if (which == 3) {                // w2b (300,200,1,3) -> [300][608]
        if (idx >= 300 * K2BP) return;
        int o = idx / K2BP, k = idx % K2BP;
        float v = 0.f;
        if (k < 600) { int kw = k / 200, c2 = k % 200; v = w2b[o * 600 + c2 * 3 + kw]; }
        g_W2b[idx] = f2tf_f(v);
    } else {                                // w2a (200,300,1,1) -> [200][320]
        if (idx >= 200 * K2AP) return;
        int o = idx / K2AP, k = idx % K2AP;
        g_W2a[idx] = (k < 300) ? f2tf_f(w2a[o * 300 + k]) : 0.f;
    }
}

// ---------------------------------------------------------------------------
// Build Xpad rows 2..101 (rows 0,1,102,103 remain zero), values tf32-rounded.
__global__ void build_x(const int* __restrict__ tok,
                        const int* __restrict__ p1m,
                        const int* __restrict__ p2m,
                        const float* __restrict__ sdp,
                        const float* __restrict__ wemb,
                        const float* __restrict__ p1e,
                        const float* __restrict__ p2e)
{
    int blk = blockIdx.x;
    int b = blk / LEN, l = blk % LEN;
    int t  = tok[b * LEN + l];
    int p1 = p1m[b * LEN + l];
    int p2 = p2m[b * LEN + l];
    float s = sdp[b * LEN + l];
    float* row = g_Xpad + ((long)(b * XROWS + l + 2)) * XC;
    int tid = threadIdx.x;
    if (tid < 250) {
        float w = wemb[(long)t * 250 + tid];
        row[tid] = f2tf_f(w);
        row[500 + tid] = f2tf_f(s * w);
    }
    if (tid < 125) {
        row[250 + tid] = f2tf_f(p1e[p1 * 125 + tid]);
        row[375 + tid] = f2tf_f(p2e[p2 * 125 + tid]);
    }
}

// ---------------------------------------------------------------------------
// tf32 GEMM: C[m,n] = bias[m] + sum_k W[m*Kp+k] * X[(n/LOUT)*sB+(n%LOUT)*sL+k]
// CTA 128x128, BK=32, 8 warps (4M x 2N), warp 32x64, mma.m16n8k8.tf32.
// cp.async 2-stage pipeline; smem tiles [row][k] stride 36 (conflict-free).
// Inputs are pre-tf32; no conversion in the loop.
// ---------------------------------------------------------------------------
#define STG 4608   // 128*36 floats per tile

template<int LOUT>
__global__ __launch_bounds__(256, 2)
void gemm_mma(const float* __restrict__ W, const float* __restrict__ bias,
              const float* __restrict__ X, float* __restrict__ out,
              int M, int Kp, long sB, int sL, long oB, int oL,
              int mOff, int doRelu, int cvtOut)
{
    extern __shared__ float sm[];   // [stage][A 4608 | B 4608]

    int tid = threadIdx.x;
    int lane = tid & 31;
    int warp = tid >> 5;
    int wm = warp & 3;
    int wn = warp >> 2;
    int lr = lane >> 2;
    int lc = lane & 3;
    int mBase = blockIdx.y * 128;
    int nBase = blockIdx.x * 128;

    // --- cp.async source/dest mapping ---
    // A: 16B chunks. row = (tid>>3)+32i, k-offset (tid&7)*4
    int aj = tid & 7, ar = tid >> 3;
    int aOff[4];
    unsigned aDst[4];
#pragma unroll
    for (int i = 0; i < 4; i++) {
        int row = ar + 32 * i;
        aOff[i] = (mBase + row) * Kp + aj * 4;
        aDst[i] = (unsigned)__cvta_generic_to_shared(sm + row * 36 + aj * 4);
    }
    // B: 8B chunks. col = (tid>>4)+16i, k-offset (tid&15)*2
    int bj = tid & 15, br = tid >> 4;
    long bOff[8];
    unsigned bDst[8];
#pragma unroll
    for (int i = 0; i < 8; i++) {
        int col = br + 16 * i;
        int n = nBase + col;
        int bb = n / LOUT, ll = n % LOUT;
        bOff[i] = (long)bb * sB + (long)ll * sL + bj * 2;
        bDst[i] = (unsigned)__cvta_generic_to_shared(sm + STG + col * 36 + bj * 2);
    }

    float acc[2][8][4];
#pragma unroll
    for (int i = 0; i < 2; i++)
#pragma unroll
        for (int j = 0; j < 8; j++)
#pragma unroll
            for (int q = 0; q < 4; q++) acc[i][j][q] = 0.f;

    int nCh = Kp >> 5;
    const unsigned stageB = 2u * STG * 4u;   // bytes per stage

    // prologue: stage 0
#pragma unroll
    for (int i = 0; i < 4; i++)
        asm volatile("cp.async.cg.shared.global [%0],[%1],16;"
                     :: "r"(aDst[i]), "l"(W + aOff[i]));
#pragma unroll
    for (int i = 0; i < 8; i++)
        asm volatile("cp.async.ca.shared.global [%0],[%1],8;"
                     :: "r"(bDst[i]), "l"(X + bOff[i]));
    asm volatile("cp.async.commit_group;");

    for (int c = 0; c < nCh; c++) {
        if (c + 1 < nCh) {
            unsigned so = ((c + 1) & 1) ? stageB : 0u;
            int ko = (c + 1) * 32;
#pragma unroll
            for (int i = 0; i < 4; i++)
                asm volatile("cp.async.cg.shared.global [%0],[%1],16;"
                             :: "r"(aDst[i] + so), "l"(W + aOff[i] + ko));
#pragma unroll
            for (int i = 0; i < 8; i++)
                asm volatile("cp.async.ca.shared.global [%0],[%1],8;"
                             :: "r"(bDst[i] + so), "l"(X + bOff[i] + ko));
            asm volatile("cp.async.commit_group;");
            asm volatile("cp.async.wait_group 1;");
        } else {
            asm volatile("cp.async.wait_group 0;");
        }
        __syncthreads();

        const float* As = sm + (c & 1) * 2 * STG;
        const float* Bs = As + STG;
#pragma unroll
        for (int kk = 0; kk < 4; kk++) {
            int k0 = kk * 8;
            unsigned af[2][4];
#pragma unroll
            for (int mi = 0; mi < 2; mi++) {
                int rb = wm * 32 + mi * 16;
                af[mi][0] = __float_as_uint(As[(rb + lr) * 36 + k0 + lc]);
                af[mi][1] = __float_as_uint(As[(rb + 8 + lr) * 36 + k0 + lc]);
                af[mi][2] = __float_as_uint(As[(rb + lr) * 36 + k0 + 4 + lc]);
                af[mi][3] = __float_as_uint(As[(rb + 8 + lr) * 36 + k0 + 4 + lc]);
            }
#pragma unroll
            for (int ni = 0; ni < 8; ni++) {
                int nb = wn * 64 + ni * 8;
                unsigned b0 = __float_as_uint(Bs[(nb + lr) * 36 + k0 + lc]);
                unsigned b1 = __float_as_uint(Bs[(nb + lr) * 36 + k0 + 4 + lc]);
#pragma unroll
                for (int mi = 0; mi < 2; mi++) {
                    asm volatile(
                        "mma.sync.aligned.m16n8k8.row.col.f32.tf32.tf32.f32 "
                        "{%0,%1,%2,%3}, {%4,%5,%6,%7}, {%8,%9}, {%0,%1,%2,%3};"
                        : "+f"(acc[mi][ni][0]), "+f"(acc[mi][ni][1]),
                          "+f"(acc[mi][ni][2]), "+f"(acc[mi][ni][3])
                        : "r"(af[mi][0]), "r"(af[mi][1]),
                          "r"(af[mi][2]), "r"(af[mi][3]),
                          "r"(b0), "r"(b1));
                }
            }
        }
        __syncthreads();
    }

    // epilogue
#pragma unroll
    for (int mi = 0; mi < 2; mi++) {
        int r0 = mBase + wm * 32 + mi * 16 + lr;
        int r1 = r0 + 8;
        float bv0 = (r0 < M) ? bias[r0] : 0.f;
        float bv1 = (r1 < M) ? bias[r1] : 0.f;
#pragma unroll
        for (int ni = 0; ni < 8; ni++) {
            int cb = nBase + wn * 64 + ni * 8 + lc * 2;
#pragma unroll
            for (int cc = 0; cc < 2; cc++) {
                int n = cb + cc;
                int b2 = n / LOUT, l2 = n % LOUT;
                long base = (long)b2 * oB + (long)l2 * oL + mOff;
                if (r0 < M) {
                    float v = acc[mi][ni][cc] + bv0;
                    if (doRelu) v = fmaxf(v, 0.f);
                    if (cvtOut) v = f2tf_f(v);
                    out[base + r0] = v;
                }
                if (r1 < M) {
                    float v = acc[mi][ni][2 + cc] + bv1;
                    if (doRelu) v = fmaxf(v, 0.f);
                    if (cvtOut) v = f2tf_f(v);
                    out[base + r1] = v;
                }
            }
        }
    }
}

// maxpool width 2 over l, output tf32-rounded (feeds conv2a GEMM)
__global__ void pool1()
{
    int blk = blockIdx.x;
    int b = blk / 50, p = blk % 50;
    const float* r0 = g_O1 + ((long)b * LEN + 2 * p) * 300;
    float* dst = g_P + ((long)b * 50 + p) * 300;
    for (int c = threadIdx.x; c < 300; c += blockDim.x)
        dst[c] = f2tf_f(fmaxf(r0[c], r0[300 + c]));
}

// max over all 50 positions
__global__ void pool3()
{
    int b = blockIdx.x;
    for (int c = threadIdx.x; c < 300; c += blockDim.x) {
        const float* src = g_O3 + (long)b * 15000 + c;
        float mx = src[0];
        for (int p = 1; p < 50; p++) mx = fmaxf(mx, src[p * 300]);
        g_H[b * 300 + c] = mx;
    }
}

// FC chain: 300 -> 100 (relu) -> 50 (relu) -> 15  (exact fp32)
__global__ void fc_chain(const float* __restrict__ d1w, const float* __restrict__ d1b,
                         const float* __restrict__ d2w, const float* __restrict__ d2b,
                         const float* __restrict__ d3w, const float* __restrict__ d3b,
                         float* __restrict__ out)
{
    __shared__ float h0[300], h1[100], h2[50];
    int b = blockIdx.x, tid = threadIdx.x;
    for (int i = tid; i < 300; i += 128) h0[i] = g_H[b * 300 + i];
    __syncthreads();
    if (tid < 100) {
        float s = d1b[tid];
        for (int k = 0; k < 300; k++) s += h0[k] * d1w[k * 100 + tid];
        h1[tid] = fmaxf(s, 0.f);
    }
    __syncthreads();
    if (tid < 50) {
        float s = d2b[tid];
        for (int k = 0; k < 100; k++) s += h1[k] * d2w[k * 50 + tid];
        h2[tid] = fmaxf(s, 0.f);
    }
    __syncthreads();
    if (tid < 15) {
        float s = d3b[tid];
        for (int k = 0; k < 50; k++) s += h2[k] * d3w[k * 15 + tid];
        out[b * 15 + tid] = s;
    }
}

extern "C" void kernel_launch(void* const* d_in, const int* in_sizes, int n_in,
                              void* d_out, int out_size)
{
    const int*   tok  = (const int*)  d_in[0];
    const int*   p1m  = (const int*)  d_in[1];
    const int*   p2m  = (const int*)  d_in[2];
    const float* sdp  = (const float*)d_in[3];
    const float* wemb = (const float*)d_in[4];
    const float* p1e  = (const float*)d_in[5];
    const float* p2e  = (const float*)d_in[6];
    const float* w11  = (const float*)d_in[7];
    const float* b11  = (const float*)d_in[8];
    const float* w13  = (const float*)d_in[9];
    const float* b13  = (const float*)d_in[10];
    const float* w15  = (const float*)d_in[11];
    const float* b15  = (const float*)d_in[12];
    const float* w2a  = (const float*)d_in[13];
    const float* b2a  = (const float*)d_in[14];
    const float* w2b  = (const float*)d_in[15];
    const float* b2b  = (const float*)d_in[16];
    const float* d1w  = (const float*)d_in[17];
    const float* d1b  = (const float*)d_in[18];
    const float* d2w  = (const float*)d_in[19];
    const float* d2b  = (const float*)d_in[20];
    const float* d3w  = (const float*)d_in[21];
    const float* d3b  = (const float*)d_in[22];

    float *Xpad, *O1, *P, *A2, *O3, *W1, *W3, *W5, *W2a, *W2b;
    cudaGetSymbolAddress((void**)&Xpad, g_Xpad);
    cudaGetSymbolAddress((void**)&O1,  g_O1);
    cudaGetSymbolAddress((void**)&P,   g_P);
    cudaGetSymbolAddress((void**)&A2,  g_A2);
    cudaGetSymbolAddress((void**)&O3,  g_O3);
    cudaGetSymbolAddress((void**)&W1,  g_W1);
    cudaGetSymbolAddress((void**)&W3,  g_W3);
    cudaGetSymbolAddress((void**)&W5,  g_W5);
    cudaGetSymbolAddress((void**)&W2a, g_W2a);
    cudaGetSymbolAddress((void**)&W2b, g_W2b);

    const int SMEM = 2 * 2 * STG * 4;   // 73728 B
    cudaFuncSetAttribute(gemm_mma<100>, cudaFuncAttributeMaxDynamicSharedMemorySize, SMEM);
    cudaFuncSetAttribute(gemm_mma<50>,  cudaFuncAttributeMaxDynamicSharedMemorySize, SMEM);

    prep_weights<<<dim3((377600 + 255) / 256, 5), 256>>>(w11, w13, w15, w2a, w2b);

    build_x<<<BATCH * LEN, 256>>>(tok, p1m, p2m, sdp, wemb, p1e, p2e);

    // conv1: N = 51200 -> 400 tiles, M=100 -> 1 tile
    gemm_mma<100><<<dim3(400, 1), 256, SMEM>>>(W1, b11, Xpad + 2 * 750, O1,
                                               100, K1P, (long)XROWS * XC, XC,
                                               30000, 300, 0, 1, 0);
    gemm_mma<100><<<dim3(400, 1), 256, SMEM>>>(W3, b13, Xpad + 750, O1,
                                               100, K3P, (long)XROWS * XC, XC,
                                               30000, 300, 100, 1, 0);
    gemm_mma<100><<<dim3(400, 1), 256, SMEM>>>(W5, b15, Xpad, O1,
                                               100, K5P, (long)XROWS * XC, XC,
                                               30000, 300, 200, 1, 0);

    pool1<<<BATCH * 50, 256>>>();

    // conv2a (1x1): out tf32-rounded into padded A2 rows 1..50
    gemm_mma<50><<<dim3(200, 2), 256, SMEM>>>(W2a, b2a, P, A2 + 200,
                                              200, K2AP, 15000, 300,
                                              10400, 200, 0, 0, 1);

    // conv2b (kw=3, pad=1)
    gemm_mma<50><<<dim3(200, 3), 256, SMEM>>>(W2b, b2b, A2, O3,
                                              300, K2BP, 10400, 200,
                                              15000, 300, 0, 1, 0);

    pool3<<<BATCH, 256>>>();

    fc_chain<<<BATCH, 128>>>(d1w, d1b, d2w, d2b, d3w, d3b, (float*)d_out);
}